// round 15
// baseline (speedup 1.0000x reference)
#include <cuda_runtime.h>
#include <cstdint>

// Problem constants
#define BB    16
#define TT    1000
#define FTOT  481
#define NF    96
#define NN    5          // FRAME_SIZE
#define NCOEF 30         // N*N + N
#define TF    (TT * NF)  // 96000

#define NSOLVE      (BB * TF)                 // 1,536,000 solve systems
#define SOLVE_BLKS  (NSOLVE / 128)            // 12000 (exact)
#define NCOPY       (BB * TT * (FTOT - NF))   // 6,160,000 pass-through float2
#define COPY_BLKS   ((NCOPY + 127) / 128)     // 48125
#define PER_ROW     (FTOT - NF)               // 385

struct cplx { float re, im; };

__device__ __forceinline__ cplx cmul(cplx a, cplx b) {
    return { a.re * b.re - a.im * b.im, a.re * b.im + a.im * b.re };
}
__device__ __forceinline__ cplx csub(cplx a, cplx b) {
    return { a.re - b.re, a.im - b.im };
}
__device__ __forceinline__ cplx cdiv(cplx a, cplx b) {
    float inv = __frcp_rn(b.re * b.re + b.im * b.im);
    return { (a.re * b.re + a.im * b.im) * inv,
             (a.im * b.re - a.re * b.im) * inv };
}
__device__ __forceinline__ float cabs2(cplx a) { return a.re * a.re + a.im * a.im; }

__device__ __forceinline__ uint32_t smem_u32(const void* p) {
    uint32_t a;
    asm("{ .reg .u64 t; cvta.to.shared.u64 t, %1; cvt.u32.u64 %0, t; }"
        : "=r"(a) : "l"(p));
    return a;
}

// Rare fallback: full Gaussian elimination with partial pivoting.
// Reloads the system from coefs (L2-hot: same lines were just read).
__device__ __noinline__ void solve_pivoted(const float2* __restrict__ coefs,
                                           int base, cplx w[NN]) {
    cplx A[NN][NN];
    cplx r[NN];
#pragma unroll
    for (int n = 0; n < NN; n++)
#pragma unroll
        for (int m = 0; m < NN; m++) {
            float2 v = coefs[base + (n * NN + m) * TF];
            A[n][m] = { v.x, v.y };
        }
#pragma unroll
    for (int n = 0; n < NN; n++) {
        float2 v = coefs[base + (NN * NN + n) * TF];
        r[n] = { v.x, v.y };
    }

#pragma unroll
    for (int k = 0; k < NN; k++) {
#pragma unroll
        for (int i = k + 1; i < NN; i++) {
            if (cabs2(A[i][k]) > cabs2(A[k][k])) {
#pragma unroll
                for (int j = k; j < NN; j++) {
                    cplx tmp = A[k][j]; A[k][j] = A[i][j]; A[i][j] = tmp;
                }
                cplx tmp = r[k]; r[k] = r[i]; r[i] = tmp;
            }
        }
        float pinv = __frcp_rn(cabs2(A[k][k]));
        cplx prec = { A[k][k].re * pinv, -A[k][k].im * pinv };
#pragma unroll
        for (int i = k + 1; i < NN; i++) {
            cplx fac = cmul(A[i][k], prec);
#pragma unroll
            for (int j = k + 1; j < NN; j++)
                A[i][j] = csub(A[i][j], cmul(fac, A[k][j]));
            r[i] = csub(r[i], cmul(fac, r[k]));
        }
    }
#pragma unroll
    for (int k = NN - 1; k >= 0; k--) {
        cplx s = r[k];
#pragma unroll
        for (int j = NN - 1; j > k; j--)
            s = csub(s, cmul(A[k][j], w[j]));
        w[k] = cdiv(s, A[k][k]);
    }
}

// Single kernel, CTA-level role split (no per-thread divergence):
//   blocks [0, SOLVE_BLKS)          : dense solve mapping over (b, t, f<96)
//   blocks [SOLVE_BLKS, +COPY_BLKS) : pass-through copy of f in [96, 481)
__global__ __launch_bounds__(128, 8)
void mfwf_fused_kernel(const float2* __restrict__ spec,
                       const float2* __restrict__ coefs,
                       float2* __restrict__ out) {
    int tid = threadIdx.x;

    if (blockIdx.x >= SOLVE_BLKS) {
        // ================= copy CTA =================
        int c = (blockIdx.x - SOLVE_BLKS) * 128 + tid;
        if (c < NCOPY) {
            int row = c / PER_ROW;
            int j   = c - row * PER_ROW;
            int idx = row * FTOT + NF + j;
            out[idx] = spec[idx];
        }
        return;
    }

    // ================= solve CTA =================
    __shared__ float2 s_r[NN][128];     // rss
    __shared__ float2 s_tap[NN][128];   // spec FIR taps

    int s = blockIdx.x * 128 + tid;     // dense over [0, NSOLVE)
    int b  = s / TF;
    int tf = s - b * TF;
    int t  = tf / NF;
    int f  = tf - t * NF;
    int base = b * NCOEF * TF + tf;

    // ---- Group 0: stage rss into smem ----
#pragma unroll
    for (int n = 0; n < NN; n++) {
        uint32_t saddr = smem_u32(&s_r[n][tid]);
        const float2* gptr = &coefs[base + (NN * NN + n) * TF];
        asm volatile("cp.async.ca.shared.global [%0], [%1], 8;\n"
                     :: "r"(saddr), "l"(gptr) : "memory");
    }
    asm volatile("cp.async.commit_group;\n" ::: "memory");

    // ---- Group 1: stage spec FIR taps into smem ----
#pragma unroll
    for (int n = 0; n < NN; n++) {
        uint32_t saddr = smem_u32(&s_tap[n][tid]);
        int tt = t - (NN - 1) + n;
        if (tt >= 0) {
            const float2* gptr = &spec[(b * TT + tt) * FTOT + f];
            asm volatile("cp.async.ca.shared.global [%0], [%1], 8;\n"
                         :: "r"(saddr), "l"(gptr) : "memory");
        } else {
            asm volatile("st.shared.v2.f32 [%0], {%1, %2};\n"
                         :: "r"(saddr), "f"(0.f), "f"(0.f) : "memory");
        }
    }
    asm volatile("cp.async.commit_group;\n" ::: "memory");

    // ---- Load Rxx (25 complexes; only these are register-live in the LU) ----
    cplx A[NN][NN];
#pragma unroll
    for (int n = 0; n < NN; n++)
#pragma unroll
        for (int m = 0; m < NN; m++) {
            float2 v = coefs[base + (n * NN + m) * TF];
            A[n][m] = { v.x, v.y };
        }

    // ---- In-place LU (no pivoting) + stability flag; multipliers in lower tri.
    //      Keep per-step pivot reciprocal for reuse in back-substitution. ----
    bool bad = false;
    float pinv5[NN];
#pragma unroll
    for (int k = 0; k < NN; k++) {
        float pa = cabs2(A[k][k]);
        float mx = pa;
#pragma unroll
        for (int i = k + 1; i < NN; i++) mx = fmaxf(mx, cabs2(A[i][k]));
        bad = bad || (pa * 1e6f < mx);     // pivot << column max => unstable

        float pinv = __frcp_rn(pa);
        pinv5[k] = pinv;
        cplx prec = { A[k][k].re * pinv, -A[k][k].im * pinv };
#pragma unroll
        for (int i = k + 1; i < NN; i++) {
            cplx fac = cmul(A[i][k], prec);
            A[i][k] = fac;                 // store multiplier in dead slot
#pragma unroll
            for (int j = k + 1; j < NN; j++)
                A[i][j] = csub(A[i][j], cmul(fac, A[k][j]));
        }
    }

    // ---- Wait for r (group 0 done; taps group may still be in flight) ----
    asm volatile("cp.async.wait_group 1;\n" ::: "memory");

    // ---- Forward substitution: y[i] = r[i] - sum_{k<i} L[i][k] * y[k] ----
    cplx y5[NN];
#pragma unroll
    for (int i = 0; i < NN; i++) {
        float2 v = s_r[i][tid];
        cplx ss = { v.x, v.y };
#pragma unroll
        for (int k = 0; k < NN; k++)
            if (k < i) ss = csub(ss, cmul(A[i][k], y5[k]));
        y5[i] = ss;
    }

    // ---- Back substitution using saved reciprocals ----
    cplx w[NN];
#pragma unroll
    for (int k = NN - 1; k >= 0; k--) {
        cplx ss = y5[k];
#pragma unroll
        for (int j = NN - 1; j > k; j--)
            ss = csub(ss, cmul(A[k][j], w[j]));
        cplx num = { ss.re * A[k][k].re + ss.im * A[k][k].im,
                     ss.im * A[k][k].re - ss.re * A[k][k].im };
        w[k] = { num.re * pinv5[k], num.im * pinv5[k] };
    }

    // ---- Rare fallback: redo with partial pivoting ----
    if (bad) solve_pivoted(coefs, base, w);

    // ---- Wait for taps, then y = sum_n tap[n] * w[n] ----
    asm volatile("cp.async.wait_group 0;\n" ::: "memory");

    cplx acc = { 0.f, 0.f };
#pragma unroll
    for (int n = 0; n < NN; n++) {
        float2 v = s_tap[n][tid];
        acc.re = fmaf(v.x, w[n].re, fmaf(-v.y, w[n].im, acc.re));
        acc.im = fmaf(v.x, w[n].im, fmaf( v.y, w[n].re, acc.im));
    }

    out[(b * TT + t) * FTOT + f] = make_float2(acc.re, acc.im);
}

extern "C" void kernel_launch(void* const* d_in, const int* in_sizes, int n_in,
                              void* d_out, int out_size) {
    const float2* spec  = (const float2*)d_in[0];
    const float2* coefs = (const float2*)d_in[1];
    float2* out = (float2*)d_out;

    int blocks = SOLVE_BLKS + COPY_BLKS;   // 12000 + 48125 = 60125
    mfwf_fused_kernel<<<blocks, 128>>>(spec, coefs, out);
}

// round 16
// speedup vs baseline: 1.1628x; 1.1628x over previous
#include <cuda_runtime.h>
#include <cstdint>

// Problem constants
#define BB    16
#define TT    1000
#define FTOT  481
#define NF    96
#define NN    5          // FRAME_SIZE
#define NCOEF 30         // N*N + N
#define TF    (TT * NF)  // 96000

#define NSOLVE      (BB * TF)                 // 1,536,000 solve systems
#define SOLVE_BLKS  (NSOLVE / 128)            // 12000 (exact)
#define NCOPY       (BB * TT * (FTOT - NF))   // 6,160,000 pass-through float2
#define COPY_BLKS   ((NCOPY + 127) / 128)     // 48125
#define PER_ROW     (FTOT - NF)               // 385
#define GRID_BLKS   60160                     // ceil-pad so both roles covered

struct cplx { float re, im; };

__device__ __forceinline__ cplx cmul(cplx a, cplx b) {
    return { a.re * b.re - a.im * b.im, a.re * b.im + a.im * b.re };
}
__device__ __forceinline__ cplx csub(cplx a, cplx b) {
    return { a.re - b.re, a.im - b.im };
}
__device__ __forceinline__ cplx cdiv(cplx a, cplx b) {
    float inv = __frcp_rn(b.re * b.re + b.im * b.im);
    return { (a.re * b.re + a.im * b.im) * inv,
             (a.im * b.re - a.re * b.im) * inv };
}
__device__ __forceinline__ float cabs2(cplx a) { return a.re * a.re + a.im * a.im; }

__device__ __forceinline__ uint32_t smem_u32(const void* p) {
    uint32_t a;
    asm("{ .reg .u64 t; cvta.to.shared.u64 t, %1; cvt.u32.u64 %0, t; }"
        : "=r"(a) : "l"(p));
    return a;
}

// Rare fallback: full Gaussian elimination with partial pivoting.
// Reloads the system from coefs (L2-hot: same lines were just read).
__device__ __noinline__ void solve_pivoted(const float2* __restrict__ coefs,
                                           int base, cplx w[NN]) {
    cplx A[NN][NN];
    cplx r[NN];
#pragma unroll
    for (int n = 0; n < NN; n++)
#pragma unroll
        for (int m = 0; m < NN; m++) {
            float2 v = coefs[base + (n * NN + m) * TF];
            A[n][m] = { v.x, v.y };
        }
#pragma unroll
    for (int n = 0; n < NN; n++) {
        float2 v = coefs[base + (NN * NN + n) * TF];
        r[n] = { v.x, v.y };
    }

#pragma unroll
    for (int k = 0; k < NN; k++) {
#pragma unroll
        for (int i = k + 1; i < NN; i++) {
            if (cabs2(A[i][k]) > cabs2(A[k][k])) {
#pragma unroll
                for (int j = k; j < NN; j++) {
                    cplx tmp = A[k][j]; A[k][j] = A[i][j]; A[i][j] = tmp;
                }
                cplx tmp = r[k]; r[k] = r[i]; r[i] = tmp;
            }
        }
        float pinv = __frcp_rn(cabs2(A[k][k]));
        cplx prec = { A[k][k].re * pinv, -A[k][k].im * pinv };
#pragma unroll
        for (int i = k + 1; i < NN; i++) {
            cplx fac = cmul(A[i][k], prec);
#pragma unroll
            for (int j = k + 1; j < NN; j++)
                A[i][j] = csub(A[i][j], cmul(fac, A[k][j]));
            r[i] = csub(r[i], cmul(fac, r[k]));
        }
    }
#pragma unroll
    for (int k = NN - 1; k >= 0; k--) {
        cplx s = r[k];
#pragma unroll
        for (int j = NN - 1; j > k; j--)
            s = csub(s, cmul(A[k][j], w[j]));
        w[k] = cdiv(s, A[k][k]);
    }
}

// Single kernel, CTA-level role split INTERLEAVED in bid space:
//   bid % 5 == 0 -> solve CTA (dense over (b, t, f<96)); ~1 in 5 blocks
//   bid % 5 != 0 -> copy CTA  (pass-through f in [96, 481))
// At any instant each SM holds a mix of compute CTAs and streaming CTAs:
// copy warps keep DRAM busy through solve warps' load-latency stalls.
__global__ __launch_bounds__(128, 8)
void mfwf_fused_kernel(const float2* __restrict__ spec,
                       const float2* __restrict__ coefs,
                       float2* __restrict__ out) {
    int tid = threadIdx.x;
    int bid = blockIdx.x;
    int q = bid / 5;

    if (bid % 5 != 0) {
        // ================= copy CTA =================
        int cid = bid - q - 1;            // dense copy-block index
        if (cid >= COPY_BLKS) return;
        int c = cid * 128 + tid;
        if (c < NCOPY) {
            int row = c / PER_ROW;
            int j   = c - row * PER_ROW;
            int idx = row * FTOT + NF + j;
            out[idx] = spec[idx];
        }
        return;
    }

    // ================= solve CTA =================
    if (q >= SOLVE_BLKS) return;
    __shared__ float2 s_r[NN][128];     // rss
    __shared__ float2 s_tap[NN][128];   // spec FIR taps

    int s = q * 128 + tid;              // dense over [0, NSOLVE)
    int b  = s / TF;
    int tf = s - b * TF;
    int t  = tf / NF;
    int f  = tf - t * NF;
    int base = b * NCOEF * TF + tf;

    // ---- Group 0: stage rss into smem ----
#pragma unroll
    for (int n = 0; n < NN; n++) {
        uint32_t saddr = smem_u32(&s_r[n][tid]);
        const float2* gptr = &coefs[base + (NN * NN + n) * TF];
        asm volatile("cp.async.ca.shared.global [%0], [%1], 8;\n"
                     :: "r"(saddr), "l"(gptr) : "memory");
    }
    asm volatile("cp.async.commit_group;\n" ::: "memory");

    // ---- Group 1: stage spec FIR taps into smem ----
#pragma unroll
    for (int n = 0; n < NN; n++) {
        uint32_t saddr = smem_u32(&s_tap[n][tid]);
        int tt = t - (NN - 1) + n;
        if (tt >= 0) {
            const float2* gptr = &spec[(b * TT + tt) * FTOT + f];
            asm volatile("cp.async.ca.shared.global [%0], [%1], 8;\n"
                         :: "r"(saddr), "l"(gptr) : "memory");
        } else {
            asm volatile("st.shared.v2.f32 [%0], {%1, %2};\n"
                         :: "r"(saddr), "f"(0.f), "f"(0.f) : "memory");
        }
    }
    asm volatile("cp.async.commit_group;\n" ::: "memory");

    // ---- Load Rxx (25 complexes; only these are register-live in the LU) ----
    cplx A[NN][NN];
#pragma unroll
    for (int n = 0; n < NN; n++)
#pragma unroll
        for (int m = 0; m < NN; m++) {
            float2 v = coefs[base + (n * NN + m) * TF];
            A[n][m] = { v.x, v.y };
        }

    // ---- In-place LU (no pivoting) + stability flag; multipliers in lower tri.
    //      Keep per-step pivot reciprocal for reuse in back-substitution. ----
    bool bad = false;
    float pinv5[NN];
#pragma unroll
    for (int k = 0; k < NN; k++) {
        float pa = cabs2(A[k][k]);
        float mx = pa;
#pragma unroll
        for (int i = k + 1; i < NN; i++) mx = fmaxf(mx, cabs2(A[i][k]));
        bad = bad || (pa * 1e6f < mx);     // pivot << column max => unstable

        float pinv = __frcp_rn(pa);
        pinv5[k] = pinv;
        cplx prec = { A[k][k].re * pinv, -A[k][k].im * pinv };
#pragma unroll
        for (int i = k + 1; i < NN; i++) {
            cplx fac = cmul(A[i][k], prec);
            A[i][k] = fac;                 // store multiplier in dead slot
#pragma unroll
            for (int j = k + 1; j < NN; j++)
                A[i][j] = csub(A[i][j], cmul(fac, A[k][j]));
        }
    }

    // ---- Wait for r (group 0 done; taps group may still be in flight) ----
    asm volatile("cp.async.wait_group 1;\n" ::: "memory");

    // ---- Forward substitution: y[i] = r[i] - sum_{k<i} L[i][k] * y[k] ----
    cplx y5[NN];
#pragma unroll
    for (int i = 0; i < NN; i++) {
        float2 v = s_r[i][tid];
        cplx ss = { v.x, v.y };
#pragma unroll
        for (int k = 0; k < NN; k++)
            if (k < i) ss = csub(ss, cmul(A[i][k], y5[k]));
        y5[i] = ss;
    }

    // ---- Back substitution using saved reciprocals ----
    cplx w[NN];
#pragma unroll
    for (int k = NN - 1; k >= 0; k--) {
        cplx ss = y5[k];
#pragma unroll
        for (int j = NN - 1; j > k; j--)
            ss = csub(ss, cmul(A[k][j], w[j]));
        cplx num = { ss.re * A[k][k].re + ss.im * A[k][k].im,
                     ss.im * A[k][k].re - ss.re * A[k][k].im };
        w[k] = { num.re * pinv5[k], num.im * pinv5[k] };
    }

    // ---- Rare fallback: redo with partial pivoting ----
    if (bad) solve_pivoted(coefs, base, w);

    // ---- Wait for taps, then y = sum_n tap[n] * w[n] ----
    asm volatile("cp.async.wait_group 0;\n" ::: "memory");

    cplx acc = { 0.f, 0.f };
#pragma unroll
    for (int n = 0; n < NN; n++) {
        float2 v = s_tap[n][tid];
        acc.re = fmaf(v.x, w[n].re, fmaf(-v.y, w[n].im, acc.re));
        acc.im = fmaf(v.x, w[n].im, fmaf( v.y, w[n].re, acc.im));
    }

    out[(b * TT + t) * FTOT + f] = make_float2(acc.re, acc.im);
}

extern "C" void kernel_launch(void* const* d_in, const int* in_sizes, int n_in,
                              void* d_out, int out_size) {
    const float2* spec  = (const float2*)d_in[0];
    const float2* coefs = (const float2*)d_in[1];
    float2* out = (float2*)d_out;

    mfwf_fused_kernel<<<GRID_BLKS, 128>>>(spec, coefs, out);
}

// round 17
// speedup vs baseline: 1.2826x; 1.1030x over previous
#include <cuda_runtime.h>
#include <cstdint>

// Problem constants
#define BB    16
#define TT    1000
#define FTOT  481
#define NF    96
#define NN    5          // FRAME_SIZE
#define NCOEF 30         // N*N + N
#define TF    (TT * NF)  // 96000

#define NSOLVE      (BB * TF)                 // 1,536,000 solve systems
#define SOLVE_BLKS  (NSOLVE / 128)            // 12000 (exact)
#define NCOPY       (BB * TT * (FTOT - NF))   // 6,160,000 pass-through float2
#define COPY_PER_T  4                         // elements per copy thread (MLP)
#define COPY_CHUNK  (128 * COPY_PER_T)        // 512 float2 per copy CTA
#define COPY_BLKS   ((NCOPY + COPY_CHUNK - 1) / COPY_CHUNK)   // 12032
#define PER_ROW     (FTOT - NF)               // 385
#define GRID_BLKS   (2 * COPY_BLKS)           // 24064: even=solve, odd=copy

struct cplx { float re, im; };

__device__ __forceinline__ cplx cmul(cplx a, cplx b) {
    return { a.re * b.re - a.im * b.im, a.re * b.im + a.im * b.re };
}
__device__ __forceinline__ cplx csub(cplx a, cplx b) {
    return { a.re - b.re, a.im - b.im };
}
__device__ __forceinline__ cplx cdiv(cplx a, cplx b) {
    float inv = __frcp_rn(b.re * b.re + b.im * b.im);
    return { (a.re * b.re + a.im * b.im) * inv,
             (a.im * b.re - a.re * b.im) * inv };
}
__device__ __forceinline__ float cabs2(cplx a) { return a.re * a.re + a.im * a.im; }

__device__ __forceinline__ uint32_t smem_u32(const void* p) {
    uint32_t a;
    asm("{ .reg .u64 t; cvta.to.shared.u64 t, %1; cvt.u32.u64 %0, t; }"
        : "=r"(a) : "l"(p));
    return a;
}

// Rare fallback: full Gaussian elimination with partial pivoting.
// Reloads the system from coefs (L2-hot: same lines were just read).
__device__ __noinline__ void solve_pivoted(const float2* __restrict__ coefs,
                                           int base, cplx w[NN]) {
    cplx A[NN][NN];
    cplx r[NN];
#pragma unroll
    for (int n = 0; n < NN; n++)
#pragma unroll
        for (int m = 0; m < NN; m++) {
            float2 v = coefs[base + (n * NN + m) * TF];
            A[n][m] = { v.x, v.y };
        }
#pragma unroll
    for (int n = 0; n < NN; n++) {
        float2 v = coefs[base + (NN * NN + n) * TF];
        r[n] = { v.x, v.y };
    }

#pragma unroll
    for (int k = 0; k < NN; k++) {
#pragma unroll
        for (int i = k + 1; i < NN; i++) {
            if (cabs2(A[i][k]) > cabs2(A[k][k])) {
#pragma unroll
                for (int j = k; j < NN; j++) {
                    cplx tmp = A[k][j]; A[k][j] = A[i][j]; A[i][j] = tmp;
                }
                cplx tmp = r[k]; r[k] = r[i]; r[i] = tmp;
            }
        }
        float pinv = __frcp_rn(cabs2(A[k][k]));
        cplx prec = { A[k][k].re * pinv, -A[k][k].im * pinv };
#pragma unroll
        for (int i = k + 1; i < NN; i++) {
            cplx fac = cmul(A[i][k], prec);
#pragma unroll
            for (int j = k + 1; j < NN; j++)
                A[i][j] = csub(A[i][j], cmul(fac, A[k][j]));
            r[i] = csub(r[i], cmul(fac, r[k]));
        }
    }
#pragma unroll
    for (int k = NN - 1; k >= 0; k--) {
        cplx s = r[k];
#pragma unroll
        for (int j = NN - 1; j > k; j--)
            s = csub(s, cmul(A[k][j], w[j]));
        w[k] = cdiv(s, A[k][k]);
    }
}

// Single kernel, CTA roles interleaved 1:1 in bid space:
//   even bid -> solve CTA (dense over (b, t, f<96)); q = bid/2 < 12000
//   odd  bid -> copy CTA, 4 float2 per thread (batched loads => MLP=4)
__global__ __launch_bounds__(128, 8)
void mfwf_fused_kernel(const float2* __restrict__ spec,
                       const float2* __restrict__ coefs,
                       float2* __restrict__ out) {
    int tid = threadIdx.x;
    int bid = blockIdx.x;
    int q = bid >> 1;

    if (bid & 1) {
        // ================= copy CTA: 512 float2, 4 per thread =================
        int c0 = q * COPY_CHUNK + tid;
        float2 v[COPY_PER_T];
        int idx[COPY_PER_T];
        // issue all loads first (4 outstanding per thread)
#pragma unroll
        for (int k = 0; k < COPY_PER_T; k++) {
            int c = c0 + k * 128;
            if (c < NCOPY) {
                int row = c / PER_ROW;
                int j   = c - row * PER_ROW;
                idx[k] = row * FTOT + NF + j;
                v[k] = spec[idx[k]];
            } else {
                idx[k] = -1;
            }
        }
#pragma unroll
        for (int k = 0; k < COPY_PER_T; k++)
            if (idx[k] >= 0) out[idx[k]] = v[k];
        return;
    }

    // ================= solve CTA =================
    if (q >= SOLVE_BLKS) return;
    __shared__ float2 s_r[NN][128];     // rss
    __shared__ float2 s_tap[NN][128];   // spec FIR taps

    int s = q * 128 + tid;              // dense over [0, NSOLVE)
    int b  = s / TF;
    int tf = s - b * TF;
    int t  = tf / NF;
    int f  = tf - t * NF;
    int base = b * NCOEF * TF + tf;

    // ---- Group 0: stage rss into smem ----
#pragma unroll
    for (int n = 0; n < NN; n++) {
        uint32_t saddr = smem_u32(&s_r[n][tid]);
        const float2* gptr = &coefs[base + (NN * NN + n) * TF];
        asm volatile("cp.async.ca.shared.global [%0], [%1], 8;\n"
                     :: "r"(saddr), "l"(gptr) : "memory");
    }
    asm volatile("cp.async.commit_group;\n" ::: "memory");

    // ---- Group 1: stage spec FIR taps into smem ----
#pragma unroll
    for (int n = 0; n < NN; n++) {
        uint32_t saddr = smem_u32(&s_tap[n][tid]);
        int tt = t - (NN - 1) + n;
        if (tt >= 0) {
            const float2* gptr = &spec[(b * TT + tt) * FTOT + f];
            asm volatile("cp.async.ca.shared.global [%0], [%1], 8;\n"
                         :: "r"(saddr), "l"(gptr) : "memory");
        } else {
            asm volatile("st.shared.v2.f32 [%0], {%1, %2};\n"
                         :: "r"(saddr), "f"(0.f), "f"(0.f) : "memory");
        }
    }
    asm volatile("cp.async.commit_group;\n" ::: "memory");

    // ---- Load Rxx (25 complexes; only these are register-live in the LU) ----
    cplx A[NN][NN];
#pragma unroll
    for (int n = 0; n < NN; n++)
#pragma unroll
        for (int m = 0; m < NN; m++) {
            float2 v = coefs[base + (n * NN + m) * TF];
            A[n][m] = { v.x, v.y };
        }

    // ---- In-place LU (no pivoting) + stability flag; multipliers in lower tri.
    //      Keep per-step pivot reciprocal for reuse in back-substitution. ----
    bool bad = false;
    float pinv5[NN];
#pragma unroll
    for (int k = 0; k < NN; k++) {
        float pa = cabs2(A[k][k]);
        float mx = pa;
#pragma unroll
        for (int i = k + 1; i < NN; i++) mx = fmaxf(mx, cabs2(A[i][k]));
        bad = bad || (pa * 1e6f < mx);     // pivot << column max => unstable

        float pinv = __frcp_rn(pa);
        pinv5[k] = pinv;
        cplx prec = { A[k][k].re * pinv, -A[k][k].im * pinv };
#pragma unroll
        for (int i = k + 1; i < NN; i++) {
            cplx fac = cmul(A[i][k], prec);
            A[i][k] = fac;                 // store multiplier in dead slot
#pragma unroll
            for (int j = k + 1; j < NN; j++)
                A[i][j] = csub(A[i][j], cmul(fac, A[k][j]));
        }
    }

    // ---- Wait for r (group 0 done; taps group may still be in flight) ----
    asm volatile("cp.async.wait_group 1;\n" ::: "memory");

    // ---- Forward substitution: y[i] = r[i] - sum_{k<i} L[i][k] * y[k] ----
    cplx y5[NN];
#pragma unroll
    for (int i = 0; i < NN; i++) {
        float2 v = s_r[i][tid];
        cplx ss = { v.x, v.y };
#pragma unroll
        for (int k = 0; k < NN; k++)
            if (k < i) ss = csub(ss, cmul(A[i][k], y5[k]));
        y5[i] = ss;
    }

    // ---- Back substitution using saved reciprocals ----
    cplx w[NN];
#pragma unroll
    for (int k = NN - 1; k >= 0; k--) {
        cplx ss = y5[k];
#pragma unroll
        for (int j = NN - 1; j > k; j--)
            ss = csub(ss, cmul(A[k][j], w[j]));
        cplx num = { ss.re * A[k][k].re + ss.im * A[k][k].im,
                     ss.im * A[k][k].re - ss.re * A[k][k].im };
        w[k] = { num.re * pinv5[k], num.im * pinv5[k] };
    }

    // ---- Rare fallback: redo with partial pivoting ----
    if (bad) solve_pivoted(coefs, base, w);

    // ---- Wait for taps, then y = sum_n tap[n] * w[n] ----
    asm volatile("cp.async.wait_group 0;\n" ::: "memory");

    cplx acc = { 0.f, 0.f };
#pragma unroll
    for (int n = 0; n < NN; n++) {
        float2 v = s_tap[n][tid];
        acc.re = fmaf(v.x, w[n].re, fmaf(-v.y, w[n].im, acc.re));
        acc.im = fmaf(v.x, w[n].im, fmaf( v.y, w[n].re, acc.im));
    }

    out[(b * TT + t) * FTOT + f] = make_float2(acc.re, acc.im);
}

extern "C" void kernel_launch(void* const* d_in, const int* in_sizes, int n_in,
                              void* d_out, int out_size) {
    const float2* spec  = (const float2*)d_in[0];
    const float2* coefs = (const float2*)d_in[1];
    float2* out = (float2*)d_out;

    mfwf_fused_kernel<<<GRID_BLKS, 128>>>(spec, coefs, out);
}